// round 1
// baseline (speedup 1.0000x reference)
#include <cuda_runtime.h>

#define B 32
#define S 2048
#define H 32
#define HKV 8
#define G 4            // H / HKV
#define D 128
#define SPLITS 4
#define CHUNK (S / SPLITS)   // 512
#define NWARP 8
#define SCALE 0.08838834764831845f
#define NEG -1e30f

// split-KV partial scratch (allocation-free: __device__ globals)
__device__ float g_part_o[B * HKV * SPLITS * G * D];
__device__ float g_part_m[B * HKV * SPLITS * G];
__device__ float g_part_l[B * HKV * SPLITS * G];

__global__ __launch_bounds__(256) void attn_split_kernel(
    const float* __restrict__ q,
    const float* __restrict__ knew,
    const float* __restrict__ vnew,
    const float* __restrict__ kbuf,
    const float* __restrict__ vbuf,
    const int*   __restrict__ req_to_token,
    const int*   __restrict__ seq_lens,
    const int*   __restrict__ out_cache_loc)
{
    const int bh    = blockIdx.x;           // b * HKV + kh
    const int b     = bh / HKV;
    const int kh    = bh % HKV;
    const int split = blockIdx.y;
    const int tid   = threadIdx.x;
    const int lane  = tid & 31;
    const int warp  = tid >> 5;

    const int seq_len = seq_lens[b];
    const int s0      = split * CHUNK;
    const int nt      = min(seq_len - s0, CHUNK);
    const int pbase   = (bh * SPLITS + split) * G;

    __shared__ float sc[G][CHUNK];          // scores -> probs (8 KB)
    __shared__ float red[NWARP][G * D];     // per-warp V accumulators (16 KB)
    __shared__ float ml_s[2][G];

    if (nt <= 0) {
        for (int i = tid; i < G * D; i += 256) g_part_o[(size_t)pbase * D + i] = 0.f;
        if (tid < G) { g_part_m[pbase + tid] = NEG; g_part_l[pbase + tid] = 0.f; }
        return;
    }

    const int out_loc = out_cache_loc[b];

    // q (scaled) in registers: one float4 per head per lane
    float4 qv[G];
    #pragma unroll
    for (int g = 0; g < G; g++) {
        float4 t = *(const float4*)(q + ((size_t)b * H + kh * G + g) * D + lane * 4);
        qv[g] = make_float4(t.x * SCALE, t.y * SCALE, t.z * SCALE, t.w * SCALE);
    }

    const float* knew_ptr = knew + ((size_t)b * HKV + kh) * D;
    const float* vnew_ptr = vnew + ((size_t)b * HKV + kh) * D;
    const int*   rtab     = req_to_token + (size_t)b * S + s0;

    // ---------- Pass 1: QK^T scores (one warp per token) ----------
    for (int t = warp; t < nt; t += NWARP) {
        const int loc = rtab[t];
        const float* kp = (loc == out_loc) ? knew_ptr
                                           : (kbuf + ((size_t)loc * HKV + kh) * D);
        float4 k4 = *(const float4*)(kp + lane * 4);
        float sg[G];
        #pragma unroll
        for (int g = 0; g < G; g++) {
            float d0 = k4.x * qv[g].x + k4.y * qv[g].y + k4.z * qv[g].z + k4.w * qv[g].w;
            #pragma unroll
            for (int off = 16; off > 0; off >>= 1)
                d0 += __shfl_xor_sync(0xffffffffu, d0, off);
            sg[g] = d0;
        }
        if (lane == 0) {
            sc[0][t] = sg[0]; sc[1][t] = sg[1]; sc[2][t] = sg[2]; sc[3][t] = sg[3];
        }
    }
    __syncthreads();

    // ---------- Pass 2: per-head max & sum-exp (warps 0..3, head = warp) ----------
    if (warp < G) {
        const int g = warp;
        float m = NEG;
        for (int t = lane; t < nt; t += 32) m = fmaxf(m, sc[g][t]);
        #pragma unroll
        for (int off = 16; off > 0; off >>= 1)
            m = fmaxf(m, __shfl_xor_sync(0xffffffffu, m, off));
        float l = 0.f;
        for (int t = lane; t < nt; t += 32) {
            float e = __expf(sc[g][t] - m);
            sc[g][t] = e;
            l += e;
        }
        #pragma unroll
        for (int off = 16; off > 0; off >>= 1)
            l += __shfl_xor_sync(0xffffffffu, l, off);
        if (lane == 0) { ml_s[0][g] = m; ml_s[1][g] = l; }
    }
    __syncthreads();

    // ---------- Pass 3: P @ V (one warp per token, register accumulate) ----------
    float4 acc[G];
    #pragma unroll
    for (int g = 0; g < G; g++) acc[g] = make_float4(0.f, 0.f, 0.f, 0.f);

    for (int t = warp; t < nt; t += NWARP) {
        const int loc = rtab[t];
        const float* vp = (loc == out_loc) ? vnew_ptr
                                           : (vbuf + ((size_t)loc * HKV + kh) * D);
        float4 v4 = *(const float4*)(vp + lane * 4);
        #pragma unroll
        for (int g = 0; g < G; g++) {
            const float p = sc[g][t];      // smem broadcast
            acc[g].x += p * v4.x; acc[g].y += p * v4.y;
            acc[g].z += p * v4.z; acc[g].w += p * v4.w;
        }
    }
    // deterministic cross-warp reduction via smem
    #pragma unroll
    for (int g = 0; g < G; g++)
        *(float4*)&red[warp][g * D + lane * 4] = acc[g];
    __syncthreads();

    for (int i = tid; i < G * D; i += 256) {
        float s = red[0][i];
        #pragma unroll
        for (int w = 1; w < NWARP; w++) s += red[w][i];
        g_part_o[(size_t)pbase * D + i] = s;
    }
    if (tid < G) {
        g_part_m[pbase + tid] = ml_s[0][tid];
        g_part_l[pbase + tid] = ml_s[1][tid];
    }
}

// merge SPLITS partials per (b, kh): one thread per (g, d)
__global__ __launch_bounds__(512) void reduce_kernel(float* __restrict__ out)
{
    const int bh  = blockIdx.x;             // b * HKV + kh
    const int b   = bh / HKV;
    const int kh  = bh % HKV;
    const int tid = threadIdx.x;
    const int g   = tid >> 7;
    const int d   = tid & 127;

    float m = NEG;
    #pragma unroll
    for (int sp = 0; sp < SPLITS; sp++)
        m = fmaxf(m, g_part_m[(bh * SPLITS + sp) * G + g]);

    float L = 0.f, o = 0.f;
    #pragma unroll
    for (int sp = 0; sp < SPLITS; sp++) {
        const int   pi = (bh * SPLITS + sp) * G + g;
        const float w  = __expf(g_part_m[pi] - m);
        L += g_part_l[pi] * w;
        o += g_part_o[(size_t)pi * D + d] * w;
    }
    out[((size_t)b * H + kh * G + g) * D + d] = o / L;
}

extern "C" void kernel_launch(void* const* d_in, const int* in_sizes, int n_in,
                              void* d_out, int out_size)
{
    const float* q        = (const float*)d_in[0];
    const float* knew     = (const float*)d_in[1];
    const float* vnew     = (const float*)d_in[2];
    const float* kbuf     = (const float*)d_in[3];
    const float* vbuf     = (const float*)d_in[4];
    const int*   req2tok  = (const int*)d_in[5];
    const int*   seq_lens = (const int*)d_in[6];
    const int*   out_loc  = (const int*)d_in[7];
    float*       out      = (float*)d_out;

    dim3 grid(B * HKV, SPLITS);
    attn_split_kernel<<<grid, 256>>>(q, knew, vnew, kbuf, vbuf,
                                     req2tok, seq_lens, out_loc);
    reduce_kernel<<<B * HKV, 512>>>(out);
}